// round 12
// baseline (speedup 1.0000x reference)
#include <cuda_runtime.h>
#include <cuda_bf16.h>
#include <cstdint>
#include <cstddef>

#define FULLMASK 0xffffffffu

constexpr int Bc=2, Hc=8, Sc=2048, Dc=128, Mc=32768;
constexpr int NQ = Bc*Sc;          // 4096 queries per head
constexpr int TQ = 128;            // queries per CTA
constexpr int TILEK = 64;          // keys per staged tile
constexpr int KSTRB = 272;         // padded smem bytes per key row (136 bf16)
constexpr int TBYTES = TILEK*KSTRB;// 17408 per buffer
constexpr int NT = Mc/TILEK;       // 512 tiles

// smem layout (byte offsets)
constexpr int SM_KB  = 0;              // 3 x 17408 = 52224 (overlays QS region)
constexpr int SM_CI  = 65536;          // u16 cand idx [128][64] = 16384
constexpr int SM_CS  = 65536+16384;    // f32 cand scores [128][64] = 32768
constexpr int SM_TOTAL = SM_CS+32768;  // 114688 B -> 2 CTAs/SM
// epilogue overlays (QS region dead): final lists
constexpr int SM_FS = 0;               // f32 [128][16]
constexpr int SM_FI = 8192;            // i32 [128][16]

__device__ __nv_bfloat16 g_kbf[(size_t)Hc*Mc*Dc];   // 64 MB bf16 keys

static __device__ __forceinline__ void cpasync16(uint32_t dst, const void* src) {
    asm volatile("cp.async.cg.shared.global [%0], [%1], 16;" :: "r"(dst), "l"(src));
}
#define CP_COMMIT() asm volatile("cp.async.commit_group;" ::: "memory")
#define CP_WAIT1()  asm volatile("cp.async.wait_group 1;" ::: "memory")
#define CP_WAIT0()  asm volatile("cp.async.wait_group 0;" ::: "memory")

static __device__ __forceinline__ uint32_t packbf(float lo, float hi) {
    __nv_bfloat162 p = __floats2bfloat162_rn(lo, hi);
    return *reinterpret_cast<uint32_t*>(&p);
}
static __device__ __forceinline__ void mma16816(float& c0, float& c1, float& c2, float& c3,
                                                uint32_t a0, uint32_t a1, uint32_t a2, uint32_t a3,
                                                uint32_t b0, uint32_t b1) {
    asm volatile("mma.sync.aligned.m16n8k16.row.col.f32.bf16.bf16.f32 "
                 "{%0,%1,%2,%3}, {%4,%5,%6,%7}, {%8,%9}, {%0,%1,%2,%3};"
                 : "+f"(c0), "+f"(c1), "+f"(c2), "+f"(c3)
                 : "r"(a0), "r"(a1), "r"(a2), "r"(a3), "r"(b0), "r"(b1));
}

// replace min entry of a 16-slot register list (scores fp32, idx packed 2xu16)
#define INSERT(sL, pL, thrL, sv, kv)                                             \
{   float _mn = sL[0]; int _mj = 0;                                              \
    _Pragma("unroll")                                                            \
    for (int _j = 1; _j < 16; ++_j) if (sL[_j] < _mn) { _mn = sL[_j]; _mj = _j; }\
    _Pragma("unroll")                                                            \
    for (int _j = 0; _j < 16; ++_j) if (_j == _mj) sL[_j] = (sv);                \
    _Pragma("unroll")                                                            \
    for (int _j = 0; _j < 8; ++_j) if (_j == (_mj >> 1))                         \
        pL[_j] = (_mj & 1) ? ((pL[_j] & 0x0000FFFFu) | ((uint32_t)(kv) << 16))   \
                           : ((pL[_j] & 0xFFFF0000u) | (uint32_t)(kv));          \
    _mn = sL[0];                                                                 \
    _Pragma("unroll")                                                            \
    for (int _j = 1; _j < 16; ++_j) _mn = fminf(_mn, sL[_j]);                    \
    thrL = _mn;                                                                  \
}

__global__ void __launch_bounds__(256) convert_k_kernel(const float* __restrict__ K) {
    size_t i = ((size_t)blockIdx.x*256u + threadIdx.x) * 8u;
    float4 a = *reinterpret_cast<const float4*>(K+i);
    float4 b = *reinterpret_cast<const float4*>(K+i+4);
    __nv_bfloat162* o = reinterpret_cast<__nv_bfloat162*>(g_kbf+i);
    o[0] = __floats2bfloat162_rn(a.x,a.y);
    o[1] = __floats2bfloat162_rn(a.z,a.w);
    o[2] = __floats2bfloat162_rn(b.x,b.y);
    o[3] = __floats2bfloat162_rn(b.z,b.w);
}

__global__ __launch_bounds__(256, 2)
void praxis_mma_kernel(const float* __restrict__ Q,
                       const float* __restrict__ Outp,
                       const float* __restrict__ Gate,
                       const float* __restrict__ Kmem,
                       const float* __restrict__ Vmem,
                       float* __restrict__ Out)
{
    extern __shared__ char smem[];
    float*    QSf = reinterpret_cast<float*>(smem);           // [d][q] fp32
    uint16_t* CIp = reinterpret_cast<uint16_t*>(smem + SM_CI);
    float*    CSp = reinterpret_cast<float*>(smem + SM_CS);
    float*    FSp = reinterpret_cast<float*>(smem + SM_FS);
    int*      FIp = reinterpret_cast<int*>(smem + SM_FI);

    const int tid  = threadIdx.x;
    const int wid  = tid >> 5;
    const int lane = tid & 31;
    const int h    = blockIdx.y;
    const int q0   = blockIdx.x * TQ;

    const float* KH = Kmem + (size_t)h * Mc * Dc;
    const __nv_bfloat16* KB = g_kbf + (size_t)h * Mc * Dc;

    // ---- verbatim qn loader (EXACT R2 arithmetic; reused for rescore) ----
    #define LOAD_QN()                                                            \
    {   _Pragma("unroll")                                                        \
        for (int half = 0; half < 2; ++half) {                                   \
            const int q    = tid >> 2;                                           \
            const int part = tid & 3;                                            \
            const int qrow = half * 64 + q;                                      \
            const int qg   = q0 + qrow;                                          \
            const int bq   = qg >> 11;                                           \
            const int sq   = qg & 2047;                                          \
            const float* qp = Q + ((((size_t)bq*Hc + h)*Sc + sq)*Dc) + part*32;  \
            float4 v[8]; float ss = 0.f;                                         \
            _Pragma("unroll")                                                    \
            for (int r = 0; r < 8; ++r) {                                        \
                v[r] = reinterpret_cast<const float4*>(qp)[r];                   \
                ss += v[r].x*v[r].x + v[r].y*v[r].y + v[r].z*v[r].z + v[r].w*v[r].w; \
            }                                                                    \
            ss += __shfl_xor_sync(FULLMASK, ss, 1);                              \
            ss += __shfl_xor_sync(FULLMASK, ss, 2);                              \
            const float inv = 1.0f / fmaxf(sqrtf(ss), 1e-12f);                   \
            _Pragma("unroll")                                                    \
            for (int r = 0; r < 8; ++r) {                                        \
                const int d = part*32 + r*4;                                     \
                QSf[(d+0)*TQ + qrow] = v[r].x * inv;                             \
                QSf[(d+1)*TQ + qrow] = v[r].y * inv;                             \
                QSf[(d+2)*TQ + qrow] = v[r].z * inv;                             \
                QSf[(d+3)*TQ + qrow] = v[r].w * inv;                             \
            }                                                                    \
        }                                                                        \
    }

    LOAD_QN();
    __syncthreads();

    // ---- build A fragments: warp w owns query rows 16w..16w+15 ----
    const int g  = lane >> 2;          // 0..7
    const int t4 = lane & 3;           // 0..3
    uint32_t afr[8][4];
    {
        const int rA = wid*16 + g;
        const int rB = rA + 8;
        #pragma unroll
        for (int ks = 0; ks < 8; ++ks) {
            const int k0 = t4*2 + ks*16;
            afr[ks][0] = packbf(QSf[(k0+0)*TQ + rA], QSf[(k0+1)*TQ + rA]);
            afr[ks][1] = packbf(QSf[(k0+0)*TQ + rB], QSf[(k0+1)*TQ + rB]);
            afr[ks][2] = packbf(QSf[(k0+8)*TQ + rA], QSf[(k0+9)*TQ + rA]);
            afr[ks][3] = packbf(QSf[(k0+8)*TQ + rB], QSf[(k0+9)*TQ + rB]);
        }
    }
    __syncthreads();   // QS reads done; region becomes K staging buffers

    // ---- K staging: tile t -> buffer b (1024 x 16B chunks, 4 per thread) ----
    const uint32_t kb_u32 = (uint32_t)__cvta_generic_to_shared(smem + SM_KB);
    #define LOADTILE(t, b)                                                       \
    {   _Pragma("unroll")                                                        \
        for (int _i = 0; _i < 4; ++_i) {                                         \
            const int _c = tid + 256*_i;                                         \
            const int _row = _c >> 4, _seg = _c & 15;                            \
            cpasync16(kb_u32 + (uint32_t)((b)*TBYTES + _row*KSTRB + _seg*16),    \
                      reinterpret_cast<const char*>(KB)                          \
                      + ((size_t)((t)*TILEK + _row))*256 + _seg*16);             \
        }                                                                        \
    }

    LOADTILE(0, 0) CP_COMMIT();
    LOADTILE(1, 1) CP_COMMIT();

    // ---- per-lane candidate lists: top-16 per (row, column-stream) ----
    float sA[16], sB[16]; uint32_t pA[8], pB[8];
    #pragma unroll
    for (int j = 0; j < 16; ++j) { sA[j] = -1e30f; sB[j] = -1e30f; }
    #pragma unroll
    for (int j = 0; j < 8; ++j) { pA[j] = 0xFFFFFFFFu; pB[j] = 0xFFFFFFFFu; }
    float thrA = -1e30f, thrB = -1e30f;

    // ---- main loop over 512 key tiles ----
    #pragma unroll 1
    for (int t = 0; t < NT; ++t) {
        CP_WAIT1();
        __syncthreads();
        const char* kbuf = smem + SM_KB + (t % 3) * TBYTES;
        const char* bpg  = kbuf + g*KSTRB + t4*4;

        // 4 block-pairs; per pair: 4 independent MMA chains of length 4
        // (block X k-low/k-high, block Y k-low/k-high) -> ILP for the tensor pipe
        #pragma unroll
        for (int bp2 = 0; bp2 < 4; ++bp2) {
            const char* bpx = bpg + (bp2*2    )*8*KSTRB;
            const char* bpy = bpg + (bp2*2 + 1)*8*KSTRB;
            float x0a=0.f,x1a=0.f,x2a=0.f,x3a=0.f,  x0b=0.f,x1b=0.f,x2b=0.f,x3b=0.f;
            float y0a=0.f,y1a=0.f,y2a=0.f,y3a=0.f,  y0b=0.f,y1b=0.f,y2b=0.f,y3b=0.f;
            #pragma unroll
            for (int ks = 0; ks < 4; ++ks) {
                const uint32_t xb0 = *reinterpret_cast<const uint32_t*>(bpx + ks*32);
                const uint32_t xb1 = *reinterpret_cast<const uint32_t*>(bpx + ks*32 + 16);
                mma16816(x0a,x1a,x2a,x3a, afr[ks][0],afr[ks][1],afr[ks][2],afr[ks][3], xb0,xb1);
                const uint32_t xb2 = *reinterpret_cast<const uint32_t*>(bpx + (ks+4)*32);
                const uint32_t xb3 = *reinterpret_cast<const uint32_t*>(bpx + (ks+4)*32 + 16);
                mma16816(x0b,x1b,x2b,x3b, afr[ks+4][0],afr[ks+4][1],afr[ks+4][2],afr[ks+4][3], xb2,xb3);
                const uint32_t yb0 = *reinterpret_cast<const uint32_t*>(bpy + ks*32);
                const uint32_t yb1 = *reinterpret_cast<const uint32_t*>(bpy + ks*32 + 16);
                mma16816(y0a,y1a,y2a,y3a, afr[ks][0],afr[ks][1],afr[ks][2],afr[ks][3], yb0,yb1);
                const uint32_t yb2 = *reinterpret_cast<const uint32_t*>(bpy + (ks+4)*32);
                const uint32_t yb3 = *reinterpret_cast<const uint32_t*>(bpy + (ks+4)*32 + 16);
                mma16816(y0b,y1b,y2b,y3b, afr[ks+4][0],afr[ks+4][1],afr[ks+4][2],afr[ks+4][3], yb2,yb3);
            }
            // combine split-k halves (filter-side rounding only; rescore is exact)
            const float xc0 = x0a + x0b, xc1 = x1a + x1b, xc2 = x2a + x2b, xc3 = x3a + x3b;
            const float yc0 = y0a + y0b, yc1 = y1a + y1b, yc2 = y2a + y2b, yc3 = y3a + y3b;

            const int kbX = t*TILEK + (bp2*2    )*8 + t4*2;
            const int kbY = t*TILEK + (bp2*2 + 1)*8 + t4*2;
            if (fmaxf(xc0, xc1) > thrA) {
                if (xc0 > thrA) { INSERT(sA, pA, thrA, xc0, kbX) }
                if (xc1 > thrA) { INSERT(sA, pA, thrA, xc1, kbX + 1) }
            }
            if (fmaxf(xc2, xc3) > thrB) {
                if (xc2 > thrB) { INSERT(sB, pB, thrB, xc2, kbX) }
                if (xc3 > thrB) { INSERT(sB, pB, thrB, xc3, kbX + 1) }
            }
            if (fmaxf(yc0, yc1) > thrA) {
                if (yc0 > thrA) { INSERT(sA, pA, thrA, yc0, kbY) }
                if (yc1 > thrA) { INSERT(sA, pA, thrA, yc1, kbY + 1) }
            }
            if (fmaxf(yc2, yc3) > thrB) {
                if (yc2 > thrB) { INSERT(sB, pB, thrB, yc2, kbY) }
                if (yc3 > thrB) { INSERT(sB, pB, thrB, yc3, kbY + 1) }
            }
        }

        if (t + 2 < NT) { LOADTILE(t + 2, (t + 2) % 3) }
        CP_COMMIT();
    }
    CP_WAIT0();
    __syncthreads();

    // ---- dump candidate indices (u16) ----
    {
        const int rA = wid*16 + g;
        const int rB = rA + 8;
        #pragma unroll
        for (int j = 0; j < 16; ++j) {
            CIp[rA*64 + t4*16 + j] = (uint16_t)((pA[j >> 1] >> ((j & 1) * 16)) & 0xFFFFu);
            CIp[rB*64 + t4*16 + j] = (uint16_t)((pB[j >> 1] >> ((j & 1) * 16)) & 0xFFFFu);
        }
    }
    __syncthreads();

    // ---- rebuild fp32 qn (verbatim) and rescore 64 candidates per row ----
    LOAD_QN();
    __syncthreads();
    {
        const int row  = tid >> 1;
        const int half = tid & 1;
        #pragma unroll 1
        for (int j = 0; j < 32; ++j) {
            const int idx = (int)CIp[row*64 + half*32 + j];
            const float4* kp = reinterpret_cast<const float4*>(KH + (size_t)idx * Dc);
            float s = 0.f;
            #pragma unroll
            for (int m = 0; m < 32; ++m) {
                const float4 kv = kp[m];
                s = fmaf(QSf[(4*m+0)*TQ + row], kv.x, s);
                s = fmaf(QSf[(4*m+1)*TQ + row], kv.y, s);
                s = fmaf(QSf[(4*m+2)*TQ + row], kv.z, s);
                s = fmaf(QSf[(4*m+3)*TQ + row], kv.w, s);
            }
            CSp[row*64 + half*32 + j] = s;
        }
    }
    __syncthreads();

    // ---- select top-16 of 64, tie rule (score desc, index asc) ----
    if (tid < 128) {
        #pragma unroll 1
        for (int n = 0; n < 16; ++n) {
            float bs = -1e30f; int bi = 0x7fffffff; int bj = 0;
            #pragma unroll 1
            for (int j = 0; j < 64; ++j) {
                const float v = CSp[tid*64 + j];
                const int  vi = (int)CIp[tid*64 + j];
                if (v > bs || (v == bs && vi < bi)) { bs = v; bi = vi; bj = j; }
            }
            FSp[tid*16 + n] = bs;
            FIp[tid*16 + n] = bi;
            CSp[tid*64 + bj] = -1e30f;
        }
    }
    __syncthreads();

    // ---- epilogue: gather V, weighted sum, gate blend (verbatim) ----
    const float gv = Gate[h];
    const float gg = 1.0f / (1.0f + expf(-gv));
    const float og = 1.0f - gg;
    const float* VH = Vmem + (size_t)h * Mc * Dc;

    const int r    = tid >> 1;
    const int part = tid & 1;

    float4 a[16];
    #pragma unroll
    for (int m = 0; m < 16; ++m) a[m] = make_float4(0.f, 0.f, 0.f, 0.f);

    #pragma unroll 1
    for (int j = 0; j < 16; ++j) {
        const float sj = FSp[r*16 + j];
        const int   vj = FIp[r*16 + j];
        const float4* vp = reinterpret_cast<const float4*>(VH + (size_t)vj * Dc + part * 64);
        #pragma unroll
        for (int m = 0; m < 16; ++m) {
            const float4 v = vp[m];
            a[m].x += sj * v.x; a[m].y += sj * v.y;
            a[m].z += sj * v.z; a[m].w += sj * v.w;
        }
    }
    {
        const int qg = q0 + r;
        const int bq = qg >> 11;
        const int sq = qg & 2047;
        const size_t off = (((size_t)bq * Hc + h) * Sc + sq) * Dc + part * 64;
        #pragma unroll
        for (int m = 0; m < 16; ++m) {
            const float4 o = *reinterpret_cast<const float4*>(Outp + off + 4*m);
            float4 rr;
            rr.x = gg * a[m].x + og * o.x;
            rr.y = gg * a[m].y + og * o.y;
            rr.z = gg * a[m].z + og * o.z;
            rr.w = gg * a[m].w + og * o.w;
            *reinterpret_cast<float4*>(Out + off + 4*m) = rr;
        }
    }
}

extern "C" void kernel_launch(void* const* d_in, const int* in_sizes, int n_in,
                              void* d_out, int out_size) {
    // metadata order: inputs(0), query(1), key(2), value(3), outputs(4),
    //                 gate(5), key_memories(6), value_memories(7)
    const float* query   = (const float*)d_in[1];
    const float* outputs = (const float*)d_in[4];
    const float* gate    = (const float*)d_in[5];
    const float* kmem    = (const float*)d_in[6];
    const float* vmem    = (const float*)d_in[7];
    float* out = (float*)d_out;

    const int nconv = (Hc * Mc * Dc) / (256 * 8);   // 16384 blocks
    convert_k_kernel<<<nconv, 256>>>(kmem);

    cudaFuncSetAttribute(praxis_mma_kernel,
                         cudaFuncAttributeMaxDynamicSharedMemorySize, SM_TOTAL);
    dim3 grid(NQ / TQ, Hc);   // 32 x 8 = 256 CTAs
    praxis_mma_kernel<<<grid, 256, SM_TOTAL>>>(query, outputs, gate, kmem, vmem, out);
}

// round 14
// speedup vs baseline: 4.4415x; 4.4415x over previous
#include <cuda_runtime.h>
#include <cuda_bf16.h>
#include <cstdint>
#include <cstddef>

#define FULLMASK 0xffffffffu

constexpr int Bc=2, Hc=8, Sc=2048, Dc=128, Mc=32768;
constexpr int NQ = Bc*Sc;          // 4096 queries per head
constexpr int TQ = 128;            // queries per CTA
constexpr int TILEK = 64;          // keys per staged tile
constexpr int KSTRB = 272;         // padded smem bytes per key row (136 bf16)
constexpr int TBYTES = TILEK*KSTRB;// 17408 per buffer
constexpr int NT = Mc/TILEK;       // 512 tiles

// smem layout (byte offsets)
constexpr int SM_KB  = 0;              // 3 x 17408 = 52224 (overlays QS region)
constexpr int SM_CI  = 65536;          // u16 cand idx [128][64] = 16384 (LIVE lists)
constexpr int SM_CS  = 65536+16384;    // f32 cand scores [128][64] = 32768 (LIVE lists)
constexpr int SM_TOTAL = SM_CS+32768;  // 114688 B -> 2 CTAs/SM
// epilogue overlays (QS region dead after rescore): final lists
constexpr int SM_FS = 0;               // f32 [128][16]
constexpr int SM_FI = 8192;            // i32 [128][16]

__device__ __nv_bfloat16 g_kbf[(size_t)Hc*Mc*Dc];   // 64 MB bf16 keys

static __device__ __forceinline__ void cpasync16(uint32_t dst, const void* src) {
    asm volatile("cp.async.cg.shared.global [%0], [%1], 16;" :: "r"(dst), "l"(src));
}
#define CP_COMMIT() asm volatile("cp.async.commit_group;" ::: "memory")
#define CP_WAIT1()  asm volatile("cp.async.wait_group 1;" ::: "memory")
#define CP_WAIT0()  asm volatile("cp.async.wait_group 0;" ::: "memory")

static __device__ __forceinline__ uint32_t packbf(float lo, float hi) {
    __nv_bfloat162 p = __floats2bfloat162_rn(lo, hi);
    return *reinterpret_cast<uint32_t*>(&p);
}
static __device__ __forceinline__ void mma16816(float& c0, float& c1, float& c2, float& c3,
                                                uint32_t a0, uint32_t a1, uint32_t a2, uint32_t a3,
                                                uint32_t b0, uint32_t b1) {
    asm volatile("mma.sync.aligned.m16n8k16.row.col.f32.bf16.bf16.f32 "
                 "{%0,%1,%2,%3}, {%4,%5,%6,%7}, {%8,%9}, {%0,%1,%2,%3};"
                 : "+f"(c0), "+f"(c1), "+f"(c2), "+f"(c3)
                 : "r"(a0), "r"(a1), "r"(a2), "r"(a3), "r"(b0), "r"(b1));
}

// SMEM-resident 16-slot list insert (lane-exclusive row -> race-free).
// Buffers the row in transient regs; recomputes threshold without re-reading.
static __device__ __forceinline__ void insert16(float* srow, uint16_t* irow,
                                                float& thr, float s, int kidx) {
    float v[16];
    #pragma unroll
    for (int j = 0; j < 16; ++j) v[j] = srow[j];
    float mn = v[0]; int mj = 0;
    #pragma unroll
    for (int j = 1; j < 16; ++j) if (v[j] < mn) { mn = v[j]; mj = j; }
    #pragma unroll
    for (int j = 0; j < 16; ++j) if (j == mj) { srow[j] = s; irow[j] = (uint16_t)kidx; }
    float t = s;
    #pragma unroll
    for (int j = 0; j < 16; ++j) t = fminf(t, (j == mj) ? s : v[j]);
    thr = t;
}

__global__ void __launch_bounds__(256) convert_k_kernel(const float* __restrict__ K) {
    size_t i = ((size_t)blockIdx.x*256u + threadIdx.x) * 8u;
    float4 a = *reinterpret_cast<const float4*>(K+i);
    float4 b = *reinterpret_cast<const float4*>(K+i+4);
    __nv_bfloat162* o = reinterpret_cast<__nv_bfloat162*>(g_kbf+i);
    o[0] = __floats2bfloat162_rn(a.x,a.y);
    o[1] = __floats2bfloat162_rn(a.z,a.w);
    o[2] = __floats2bfloat162_rn(b.x,b.y);
    o[3] = __floats2bfloat162_rn(b.z,b.w);
}

__global__ __launch_bounds__(256, 2)
void praxis_mma_kernel(const float* __restrict__ Q,
                       const float* __restrict__ Outp,
                       const float* __restrict__ Gate,
                       const float* __restrict__ Kmem,
                       const float* __restrict__ Vmem,
                       float* __restrict__ Out)
{
    extern __shared__ char smem[];
    float*    QSf = reinterpret_cast<float*>(smem);           // [d][q] fp32
    uint16_t* CIp = reinterpret_cast<uint16_t*>(smem + SM_CI);
    float*    CSp = reinterpret_cast<float*>(smem + SM_CS);
    float*    FSp = reinterpret_cast<float*>(smem + SM_FS);
    int*      FIp = reinterpret_cast<int*>(smem + SM_FI);

    const int tid  = threadIdx.x;
    const int wid  = tid >> 5;
    const int lane = tid & 31;
    const int h    = blockIdx.y;
    const int q0   = blockIdx.x * TQ;

    const float* KH = Kmem + (size_t)h * Mc * Dc;
    const __nv_bfloat16* KB = g_kbf + (size_t)h * Mc * Dc;

    // ---- init live candidate lists ----
    #pragma unroll
    for (int i = tid; i < TQ * 64; i += 256) { CSp[i] = -1e30f; CIp[i] = 0xFFFFu; }

    // ---- verbatim qn loader (EXACT R2 arithmetic; reused for rescore) ----
    #define LOAD_QN()                                                            \
    {   _Pragma("unroll")                                                        \
        for (int half = 0; half < 2; ++half) {                                   \
            const int q    = tid >> 2;                                           \
            const int part = tid & 3;                                            \
            const int qrow = half * 64 + q;                                      \
            const int qg   = q0 + qrow;                                          \
            const int bq   = qg >> 11;                                           \
            const int sq   = qg & 2047;                                          \
            const float* qp = Q + ((((size_t)bq*Hc + h)*Sc + sq)*Dc) + part*32;  \
            float4 v[8]; float ss = 0.f;                                         \
            _Pragma("unroll")                                                    \
            for (int r = 0; r < 8; ++r) {                                        \
                v[r] = reinterpret_cast<const float4*>(qp)[r];                   \
                ss += v[r].x*v[r].x + v[r].y*v[r].y + v[r].z*v[r].z + v[r].w*v[r].w; \
            }                                                                    \
            ss += __shfl_xor_sync(FULLMASK, ss, 1);                              \
            ss += __shfl_xor_sync(FULLMASK, ss, 2);                              \
            const float inv = 1.0f / fmaxf(sqrtf(ss), 1e-12f);                   \
            _Pragma("unroll")                                                    \
            for (int r = 0; r < 8; ++r) {                                        \
                const int d = part*32 + r*4;                                     \
                QSf[(d+0)*TQ + qrow] = v[r].x * inv;                             \
                QSf[(d+1)*TQ + qrow] = v[r].y * inv;                             \
                QSf[(d+2)*TQ + qrow] = v[r].z * inv;                             \
                QSf[(d+3)*TQ + qrow] = v[r].w * inv;                             \
            }                                                                    \
        }                                                                        \
    }

    LOAD_QN();
    __syncthreads();

    // ---- build A fragments: warp w owns query rows 16w..16w+15 ----
    const int g  = lane >> 2;          // 0..7
    const int t4 = lane & 3;           // 0..3
    const int rA = wid*16 + g;
    const int rB = rA + 8;
    uint32_t afr[8][4];
    {
        #pragma unroll
        for (int ks = 0; ks < 8; ++ks) {
            const int k0 = t4*2 + ks*16;
            afr[ks][0] = packbf(QSf[(k0+0)*TQ + rA], QSf[(k0+1)*TQ + rA]);
            afr[ks][1] = packbf(QSf[(k0+0)*TQ + rB], QSf[(k0+1)*TQ + rB]);
            afr[ks][2] = packbf(QSf[(k0+8)*TQ + rA], QSf[(k0+9)*TQ + rA]);
            afr[ks][3] = packbf(QSf[(k0+8)*TQ + rB], QSf[(k0+9)*TQ + rB]);
        }
    }
    __syncthreads();   // QS reads done; region becomes K staging buffers

    // ---- K staging: tile t -> buffer b (1024 x 16B chunks, 4 per thread) ----
    const uint32_t kb_u32 = (uint32_t)__cvta_generic_to_shared(smem + SM_KB);
    #define LOADTILE(t, b)                                                       \
    {   _Pragma("unroll")                                                        \
        for (int _i = 0; _i < 4; ++_i) {                                         \
            const int _c = tid + 256*_i;                                         \
            const int _row = _c >> 4, _seg = _c & 15;                            \
            cpasync16(kb_u32 + (uint32_t)((b)*TBYTES + _row*KSTRB + _seg*16),    \
                      reinterpret_cast<const char*>(KB)                          \
                      + ((size_t)((t)*TILEK + _row))*256 + _seg*16);             \
        }                                                                        \
    }

    LOADTILE(0, 0) CP_COMMIT();
    LOADTILE(1, 1) CP_COMMIT();

    // per-lane list base pointers (stream = t4) and threshold registers
    float*    sArow = CSp + rA*64 + t4*16;
    uint16_t* iArow = CIp + rA*64 + t4*16;
    float*    sBrow = CSp + rB*64 + t4*16;
    uint16_t* iBrow = CIp + rB*64 + t4*16;
    float thrA = -1e30f, thrB = -1e30f;

    // ---- main loop over 512 key tiles ----
    #pragma unroll 1
    for (int t = 0; t < NT; ++t) {
        CP_WAIT1();
        __syncthreads();
        const char* kbuf = smem + SM_KB + (t % 3) * TBYTES;
        const char* bpg  = kbuf + g*KSTRB + t4*4;

        // 4 block-pairs; two interleaved MMA chains (ILP=2), 8 live accumulators
        #pragma unroll 1
        for (int pb = 0; pb < 4; ++pb) {
            const char* bpx = bpg + (pb*2    )*8*KSTRB;
            const char* bpy = bpg + (pb*2 + 1)*8*KSTRB;
            float x0=0.f,x1=0.f,x2=0.f,x3=0.f;
            float y0=0.f,y1=0.f,y2=0.f,y3=0.f;
            #pragma unroll
            for (int ks = 0; ks < 8; ++ks) {
                const uint32_t xb0 = *reinterpret_cast<const uint32_t*>(bpx + ks*32);
                const uint32_t xb1 = *reinterpret_cast<const uint32_t*>(bpx + ks*32 + 16);
                mma16816(x0,x1,x2,x3, afr[ks][0],afr[ks][1],afr[ks][2],afr[ks][3], xb0,xb1);
                const uint32_t yb0 = *reinterpret_cast<const uint32_t*>(bpy + ks*32);
                const uint32_t yb1 = *reinterpret_cast<const uint32_t*>(bpy + ks*32 + 16);
                mma16816(y0,y1,y2,y3, afr[ks][0],afr[ks][1],afr[ks][2],afr[ks][3], yb0,yb1);
            }
            const int kbX = t*TILEK + (pb*2    )*8 + t4*2;
            const int kbY = t*TILEK + (pb*2 + 1)*8 + t4*2;
            if (fmaxf(fmaxf(x0,x1), fmaxf(y0,y1)) > thrA) {
                if (x0 > thrA) insert16(sArow, iArow, thrA, x0, kbX);
                if (x1 > thrA) insert16(sArow, iArow, thrA, x1, kbX + 1);
                if (y0 > thrA) insert16(sArow, iArow, thrA, y0, kbY);
                if (y1 > thrA) insert16(sArow, iArow, thrA, y1, kbY + 1);
            }
            if (fmaxf(fmaxf(x2,x3), fmaxf(y2,y3)) > thrB) {
                if (x2 > thrB) insert16(sBrow, iBrow, thrB, x2, kbX);
                if (x3 > thrB) insert16(sBrow, iBrow, thrB, x3, kbX + 1);
                if (y2 > thrB) insert16(sBrow, iBrow, thrB, y2, kbY);
                if (y3 > thrB) insert16(sBrow, iBrow, thrB, y3, kbY + 1);
            }
        }

        if (t + 2 < NT) { LOADTILE(t + 2, (t + 2) % 3) }
        CP_COMMIT();
    }
    CP_WAIT0();
    __syncthreads();
    // candidate lists are already in CSp/CIp final layout -- no dump needed

    // ---- rebuild fp32 qn (verbatim) and rescore 64 candidates per row ----
    LOAD_QN();
    __syncthreads();
    {
        const int row  = tid >> 1;
        const int half = tid & 1;
        #pragma unroll 1
        for (int j = 0; j < 32; ++j) {
            const int idx = (int)CIp[row*64 + half*32 + j];
            const float4* kp = reinterpret_cast<const float4*>(KH + (size_t)idx * Dc);
            float s = 0.f;
            #pragma unroll
            for (int m = 0; m < 32; ++m) {
                const float4 kv = kp[m];
                s = fmaf(QSf[(4*m+0)*TQ + row], kv.x, s);
                s = fmaf(QSf[(4*m+1)*TQ + row], kv.y, s);
                s = fmaf(QSf[(4*m+2)*TQ + row], kv.z, s);
                s = fmaf(QSf[(4*m+3)*TQ + row], kv.w, s);
            }
            CSp[row*64 + half*32 + j] = s;
        }
    }
    __syncthreads();

    // ---- select top-16 of 64, tie rule (score desc, index asc) ----
    if (tid < 128) {
        #pragma unroll 1
        for (int n = 0; n < 16; ++n) {
            float bs = -1e30f; int bi = 0x7fffffff; int bj = 0;
            #pragma unroll 1
            for (int j = 0; j < 64; ++j) {
                const float v = CSp[tid*64 + j];
                const int  vi = (int)CIp[tid*64 + j];
                if (v > bs || (v == bs && vi < bi)) { bs = v; bi = vi; bj = j; }
            }
            FSp[tid*16 + n] = bs;
            FIp[tid*16 + n] = bi;
            CSp[tid*64 + bj] = -1e30f;
        }
    }
    __syncthreads();

    // ---- epilogue: gather V, weighted sum, gate blend (verbatim) ----
    const float gv = Gate[h];
    const float gg = 1.0f / (1.0f + expf(-gv));
    const float og = 1.0f - gg;
    const float* VH = Vmem + (size_t)h * Mc * Dc;

    const int r    = tid >> 1;
    const int part = tid & 1;

    float4 a[16];
    #pragma unroll
    for (int m = 0; m < 16; ++m) a[m] = make_float4(0.f, 0.f, 0.f, 0.f);

    #pragma unroll 1
    for (int j = 0; j < 16; ++j) {
        const float sj = FSp[r*16 + j];
        const int   vj = FIp[r*16 + j];
        const float4* vp = reinterpret_cast<const float4*>(VH + (size_t)vj * Dc + part * 64);
        #pragma unroll
        for (int m = 0; m < 16; ++m) {
            const float4 v = vp[m];
            a[m].x += sj * v.x; a[m].y += sj * v.y;
            a[m].z += sj * v.z; a[m].w += sj * v.w;
        }
    }
    {
        const int qg = q0 + r;
        const int bq = qg >> 11;
        const int sq = qg & 2047;
        const size_t off = (((size_t)bq * Hc + h) * Sc + sq) * Dc + part * 64;
        #pragma unroll
        for (int m = 0; m < 16; ++m) {
            const float4 o = *reinterpret_cast<const float4*>(Outp + off + 4*m);
            float4 rr;
            rr.x = gg * a[m].x + og * o.x;
            rr.y = gg * a[m].y + og * o.y;
            rr.z = gg * a[m].z + og * o.z;
            rr.w = gg * a[m].w + og * o.w;
            *reinterpret_cast<float4*>(Out + off + 4*m) = rr;
        }
    }
}

extern "C" void kernel_launch(void* const* d_in, const int* in_sizes, int n_in,
                              void* d_out, int out_size) {
    // metadata order: inputs(0), query(1), key(2), value(3), outputs(4),
    //                 gate(5), key_memories(6), value_memories(7)
    const float* query   = (const float*)d_in[1];
    const float* outputs = (const float*)d_in[4];
    const float* gate    = (const float*)d_in[5];
    const float* kmem    = (const float*)d_in[6];
    const float* vmem    = (const float*)d_in[7];
    float* out = (float*)d_out;

    const int nconv = (Hc * Mc * Dc) / (256 * 8);   // 16384 blocks
    convert_k_kernel<<<nconv, 256>>>(kmem);

    cudaFuncSetAttribute(praxis_mma_kernel,
                         cudaFuncAttributeMaxDynamicSharedMemorySize, SM_TOTAL);
    dim3 grid(NQ / TQ, Hc);   // 32 x 8 = 256 CTAs
    praxis_mma_kernel<<<grid, 256, SM_TOTAL>>>(query, outputs, gate, kmem, vmem, out);
}

// round 16
// speedup vs baseline: 7.2980x; 1.6431x over previous
#include <cuda_runtime.h>
#include <cuda_bf16.h>
#include <cstdint>
#include <cstddef>

#define FULLMASK 0xffffffffu

constexpr int Bc=2, Hc=8, Sc=2048, Dc=128, Mc=32768;
constexpr int NQ = Bc*Sc;          // 4096 queries per head
constexpr int TQ = 128;            // queries per CTA
constexpr int TILEK = 64;          // keys per staged tile
constexpr int KSTRB = 272;         // padded smem bytes per key row (136 bf16)
constexpr int TBYTES = TILEK*KSTRB;// 17408 per buffer
constexpr int NT = Mc/TILEK;       // 512 tiles
constexpr int CAP = 64;            // per-row append buffer capacity
constexpr int KEEP = 24;           // compaction keep target (bf16 top-24 superset)

// smem layout (byte offsets)
constexpr int SM_KB   = 0;               // 3 x 17408 = 52224 K staging (inside QS region)
constexpr int SM_SCR  = 52224;           // compaction tracker: 128*24*4 = 12288
constexpr int SM_QEND = 65536;           // QSf region [0, 65536)
constexpr int SM_TH   = 65536;           // f32 [128]
constexpr int SM_CNT  = 66048;           // u32 [128]
constexpr int SM_CSB  = 66560;           // f32 [128][64] = 32768
constexpr int SM_CIB  = 99328;           // u16 [128][64] = 16384
constexpr int SM_TOTAL= 115712;          // 2 CTAs/SM (231424 <= 233472)
// epilogue overlays (QS region dead after rescore)
constexpr int SM_FS = 0;                 // f32 [128][16]
constexpr int SM_FI = 8192;              // i32 [128][16]

__device__ __nv_bfloat16 g_kbf[(size_t)Hc*Mc*Dc];   // 64 MB bf16 keys

static __device__ __forceinline__ void cpasync16(uint32_t dst, const void* src) {
    asm volatile("cp.async.cg.shared.global [%0], [%1], 16;" :: "r"(dst), "l"(src));
}
#define CP_COMMIT() asm volatile("cp.async.commit_group;" ::: "memory")
#define CP_WAIT1()  asm volatile("cp.async.wait_group 1;" ::: "memory")
#define CP_WAIT0()  asm volatile("cp.async.wait_group 0;" ::: "memory")

static __device__ __forceinline__ uint32_t packbf(float lo, float hi) {
    __nv_bfloat162 p = __floats2bfloat162_rn(lo, hi);
    return *reinterpret_cast<uint32_t*>(&p);
}
static __device__ __forceinline__ void mma16816(float& c0, float& c1, float& c2, float& c3,
                                                uint32_t a0, uint32_t a1, uint32_t a2, uint32_t a3,
                                                uint32_t b0, uint32_t b1) {
    asm volatile("mma.sync.aligned.m16n8k16.row.col.f32.bf16.bf16.f32 "
                 "{%0,%1,%2,%3}, {%4,%5,%6,%7}, {%8,%9}, {%0,%1,%2,%3};"
                 : "+f"(c0), "+f"(c1), "+f"(c2), "+f"(c3)
                 : "r"(a0), "r"(a1), "r"(a2), "r"(a3), "r"(b0), "r"(b1));
}

__global__ void __launch_bounds__(256) convert_k_kernel(const float* __restrict__ K) {
    size_t i = ((size_t)blockIdx.x*256u + threadIdx.x) * 8u;
    float4 a = *reinterpret_cast<const float4*>(K+i);
    float4 b = *reinterpret_cast<const float4*>(K+i+4);
    __nv_bfloat162* o = reinterpret_cast<__nv_bfloat162*>(g_kbf+i);
    o[0] = __floats2bfloat162_rn(a.x,a.y);
    o[1] = __floats2bfloat162_rn(a.z,a.w);
    o[2] = __floats2bfloat162_rn(b.x,b.y);
    o[3] = __floats2bfloat162_rn(b.z,b.w);
}

__global__ __launch_bounds__(256, 2)
void praxis_mma_kernel(const float* __restrict__ Q,
                       const float* __restrict__ Outp,
                       const float* __restrict__ Gate,
                       const float* __restrict__ Kmem,
                       const float* __restrict__ Vmem,
                       float* __restrict__ Out)
{
    extern __shared__ char smem[];
    float*    QSf = reinterpret_cast<float*>(smem);            // [d][q] fp32
    float*    SCR = reinterpret_cast<float*>(smem + SM_SCR);   // [128][24] tracker
    float*    Th  = reinterpret_cast<float*>(smem + SM_TH);    // [128]
    unsigned* Cnt = reinterpret_cast<unsigned*>(smem + SM_CNT);// [128]
    float*    CSb = reinterpret_cast<float*>(smem + SM_CSB);   // [128][64]
    uint16_t* CIb = reinterpret_cast<uint16_t*>(smem + SM_CIB);// [128][64]
    float*    FSp = reinterpret_cast<float*>(smem + SM_FS);
    int*      FIp = reinterpret_cast<int*>(smem + SM_FI);

    const int tid  = threadIdx.x;
    const int wid  = tid >> 5;
    const int lane = tid & 31;
    const int h    = blockIdx.y;
    const int q0   = blockIdx.x * TQ;

    const float* KH = Kmem + (size_t)h * Mc * Dc;
    const __nv_bfloat16* KB = g_kbf + (size_t)h * Mc * Dc;

    // ---- init thresholds / counters / append buffers ----
    for (int i = tid; i < 128; i += 256) { Th[i] = -3e38f; Cnt[i] = 0u; }
    for (int i = tid; i < 128 * CAP; i += 256) { CSb[i] = -3e38f; CIb[i] = 0; }

    // ---- verbatim qn loader (EXACT R2 arithmetic; reused for rescore) ----
    #define LOAD_QN()                                                            \
    {   _Pragma("unroll")                                                        \
        for (int half = 0; half < 2; ++half) {                                   \
            const int q    = tid >> 2;                                           \
            const int part = tid & 3;                                            \
            const int qrow = half * 64 + q;                                      \
            const int qg   = q0 + qrow;                                          \
            const int bq   = qg >> 11;                                           \
            const int sq   = qg & 2047;                                          \
            const float* qp = Q + ((((size_t)bq*Hc + h)*Sc + sq)*Dc) + part*32;  \
            float4 v[8]; float ss = 0.f;                                         \
            _Pragma("unroll")                                                    \
            for (int r = 0; r < 8; ++r) {                                        \
                v[r] = reinterpret_cast<const float4*>(qp)[r];                   \
                ss += v[r].x*v[r].x + v[r].y*v[r].y + v[r].z*v[r].z + v[r].w*v[r].w; \
            }                                                                    \
            ss += __shfl_xor_sync(FULLMASK, ss, 1);                              \
            ss += __shfl_xor_sync(FULLMASK, ss, 2);                              \
            const float inv = 1.0f / fmaxf(sqrtf(ss), 1e-12f);                   \
            _Pragma("unroll")                                                    \
            for (int r = 0; r < 8; ++r) {                                        \
                const int d = part*32 + r*4;                                     \
                QSf[(d+0)*TQ + qrow] = v[r].x * inv;                             \
                QSf[(d+1)*TQ + qrow] = v[r].y * inv;                             \
                QSf[(d+2)*TQ + qrow] = v[r].z * inv;                             \
                QSf[(d+3)*TQ + qrow] = v[r].w * inv;                             \
            }                                                                    \
        }                                                                        \
    }

    LOAD_QN();
    __syncthreads();

    // ---- build A fragments: warp w owns query rows 16w..16w+15 ----
    const int g  = lane >> 2;          // 0..7
    const int t4 = lane & 3;           // 0..3
    const int rA = wid*16 + g;
    const int rB = rA + 8;
    uint32_t afr[8][4];
    {
        #pragma unroll
        for (int ks = 0; ks < 8; ++ks) {
            const int k0 = t4*2 + ks*16;
            afr[ks][0] = packbf(QSf[(k0+0)*TQ + rA], QSf[(k0+1)*TQ + rA]);
            afr[ks][1] = packbf(QSf[(k0+0)*TQ + rB], QSf[(k0+1)*TQ + rB]);
            afr[ks][2] = packbf(QSf[(k0+8)*TQ + rA], QSf[(k0+9)*TQ + rA]);
            afr[ks][3] = packbf(QSf[(k0+8)*TQ + rB], QSf[(k0+9)*TQ + rB]);
        }
    }
    __syncthreads();   // QS reads done; region becomes K staging buffers

    // ---- K staging: tile t -> buffer b (1024 x 16B chunks, 4 per thread) ----
    const uint32_t kb_u32 = (uint32_t)__cvta_generic_to_shared(smem + SM_KB);
    #define LOADTILE(t, b)                                                       \
    {   _Pragma("unroll")                                                        \
        for (int _i = 0; _i < 4; ++_i) {                                         \
            const int _c = tid + 256*_i;                                         \
            const int _row = _c >> 4, _seg = _c & 15;                            \
            cpasync16(kb_u32 + (uint32_t)((b)*TBYTES + _row*KSTRB + _seg*16),    \
                      reinterpret_cast<const char*>(KB)                          \
                      + ((size_t)((t)*TILEK + _row))*256 + _seg*16);             \
        }                                                                        \
    }

    LOADTILE(0, 0) CP_COMMIT();
    LOADTILE(1, 1) CP_COMMIT();

    // append: slot via atomic counter; clamp guards smem (loss P ~ 1e-9)
    #define APPEND(row_, s_, k_)                                                 \
    {   const unsigned _p = atomicAdd(&Cnt[row_], 1u);                           \
        if (_p < (unsigned)CAP) {                                                \
            CSb[(row_)*CAP + _p] = (s_);                                         \
            CIb[(row_)*CAP + _p] = (uint16_t)(k_);                               \
        }                                                                        \
    }

    // ---- main loop over 512 key tiles ----
    #pragma unroll 1
    for (int t = 0; t < NT; ++t) {
        CP_WAIT1();
        __syncthreads();
        const char* kbuf = smem + SM_KB + (t % 3) * TBYTES;
        const char* bpg  = kbuf + g*KSTRB + t4*4;
        const float thA = Th[rA];
        const float thB = Th[rB];

        #pragma unroll 1
        for (int pb = 0; pb < 4; ++pb) {
            const char* bpx = bpg + (pb*2    )*8*KSTRB;
            const char* bpy = bpg + (pb*2 + 1)*8*KSTRB;
            float x0=0.f,x1=0.f,x2=0.f,x3=0.f;
            float y0=0.f,y1=0.f,y2=0.f,y3=0.f;
            #pragma unroll
            for (int ks = 0; ks < 8; ++ks) {
                const uint32_t xb0 = *reinterpret_cast<const uint32_t*>(bpx + ks*32);
                const uint32_t xb1 = *reinterpret_cast<const uint32_t*>(bpx + ks*32 + 16);
                mma16816(x0,x1,x2,x3, afr[ks][0],afr[ks][1],afr[ks][2],afr[ks][3], xb0,xb1);
                const uint32_t yb0 = *reinterpret_cast<const uint32_t*>(bpy + ks*32);
                const uint32_t yb1 = *reinterpret_cast<const uint32_t*>(bpy + ks*32 + 16);
                mma16816(y0,y1,y2,y3, afr[ks][0],afr[ks][1],afr[ks][2],afr[ks][3], yb0,yb1);
            }
            const int kbX = t*TILEK + (pb*2    )*8 + t4*2;
            const int kbY = t*TILEK + (pb*2 + 1)*8 + t4*2;
            if (x0 >= thA) APPEND(rA, x0, kbX)
            if (x1 >= thA) APPEND(rA, x1, kbX + 1)
            if (y0 >= thA) APPEND(rA, y0, kbY)
            if (y1 >= thA) APPEND(rA, y1, kbY + 1)
            if (x2 >= thB) APPEND(rB, x2, kbX)
            if (x3 >= thB) APPEND(rB, x3, kbX + 1)
            if (y2 >= thB) APPEND(rB, y2, kbY)
            if (y3 >= thB) APPEND(rB, y3, kbY + 1)
        }

        if (t + 2 < NT) { LOADTILE(t + 2, (t + 2) % 3) }
        CP_COMMIT();

        // ---- scheduled compaction (warp-local; rows are warp-exclusive) ----
        const unsigned u = (unsigned)(t + 1);
        const unsigned u3 = u / 3u;
        if ((((u & (u - 1u)) == 0u) ||
             ((u3 * 3u == u) && ((u3 & (u3 - 1u)) == 0u))) && (t + 1 < NT)) {
            __syncwarp();
            if (lane < 16) {
                const int row = wid * 16 + lane;
                float*    bs = CSb + row * CAP;
                uint16_t* bi = CIb + row * CAP;
                float*    tp = SCR + row * KEEP;
                #pragma unroll 1
                for (int j = 0; j < KEEP; ++j) tp[j] = -3e38f;
                float tmin = -3e38f;
                #pragma unroll 1
                for (int j = 0; j < CAP; ++j) {
                    const float v = bs[j];
                    if (v > tmin) {
                        int mj = 0; float mn = tp[0];
                        #pragma unroll 1
                        for (int q = 1; q < KEEP; ++q) {
                            const float w2 = tp[q];
                            if (w2 < mn) { mn = w2; mj = q; }
                        }
                        tp[mj] = v;
                        float nm = v;
                        #pragma unroll 1
                        for (int q = 0; q < KEEP; ++q) nm = fminf(nm, tp[q]);
                        tmin = nm;
                    }
                }
                // keep everything >= tmin (ties preserved), clear the rest
                int w = 0;
                #pragma unroll 1
                for (int j = 0; j < CAP; ++j) {
                    const float v = bs[j];
                    if (v >= tmin) { const uint16_t ii = bi[j]; bs[w] = v; bi[w] = ii; ++w; }
                }
                #pragma unroll 1
                for (int j = w; j < CAP; ++j) bs[j] = -3e38f;
                Th[row]  = tmin;
                Cnt[row] = (unsigned)w;
            }
            __syncwarp();
        }
    }
    CP_WAIT0();
    __syncthreads();

    // ---- rebuild fp32 qn (verbatim) and rescore candidates ----
    LOAD_QN();
    __syncthreads();
    {
        const int row  = tid >> 1;
        const int half = tid & 1;
        #pragma unroll 1
        for (int j = 0; j < 32; ++j) {
            const int sl = row*CAP + half*32 + j;
            if (CSb[sl] > -1e37f) {
                const int idx = (int)CIb[sl];
                const float4* kp = reinterpret_cast<const float4*>(KH + (size_t)idx * Dc);
                float s = 0.f;
                #pragma unroll
                for (int m = 0; m < 32; ++m) {
                    const float4 kv = kp[m];
                    s = fmaf(QSf[(4*m+0)*TQ + row], kv.x, s);
                    s = fmaf(QSf[(4*m+1)*TQ + row], kv.y, s);
                    s = fmaf(QSf[(4*m+2)*TQ + row], kv.z, s);
                    s = fmaf(QSf[(4*m+3)*TQ + row], kv.w, s);
                }
                CSb[sl] = s;
            }
        }
    }
    __syncthreads();

    // ---- select top-16, tie rule (score desc, index asc) ----
    if (tid < 128) {
        #pragma unroll 1
        for (int n = 0; n < 16; ++n) {
            float bs = -3e38f; int bi = 0x7fffffff; int bj = 0;
            #pragma unroll 1
            for (int j = 0; j < CAP; ++j) {
                const float v = CSb[tid*CAP + j];
                const int  vi = (int)CIb[tid*CAP + j];
                if (v > bs || (v == bs && vi < bi)) { bs = v; bi = vi; bj = j; }
            }
            FSp[tid*16 + n] = bs;
            FIp[tid*16 + n] = bi;
            CSb[tid*CAP + bj] = -3e38f;
        }
    }
    __syncthreads();

    // ---- epilogue: gather V, weighted sum, gate blend (verbatim) ----
    const float gv = Gate[h];
    const float gg = 1.0f / (1.0f + expf(-gv));
    const float og = 1.0f - gg;
    const float* VH = Vmem + (size_t)h * Mc * Dc;

    const int r    = tid >> 1;
    const int part = tid & 1;

    float4 a[16];
    #pragma unroll
    for (int m = 0; m < 16; ++m) a[m] = make_float4(0.f, 0.f, 0.f, 0.f);

    #pragma unroll 1
    for (int j = 0; j < 16; ++j) {
        const float sj = FSp[r*16 + j];
        const int   vj = FIp[r*16 + j];
        const float4* vp = reinterpret_cast<const float4*>(VH + (size_t)vj * Dc + part * 64);
        #pragma unroll
        for (int m = 0; m < 16; ++m) {
            const float4 v = vp[m];
            a[m].x += sj * v.x; a[m].y += sj * v.y;
            a[m].z += sj * v.z; a[m].w += sj * v.w;
        }
    }
    {
        const int qg = q0 + r;
        const int bq = qg >> 11;
        const int sq = qg & 2047;
        const size_t off = (((size_t)bq * Hc + h) * Sc + sq) * Dc + part * 64;
        #pragma unroll
        for (int m = 0; m < 16; ++m) {
            const float4 o = *reinterpret_cast<const float4*>(Outp + off + 4*m);
            float4 rr;
            rr.x = gg * a[m].x + og * o.x;
            rr.y = gg * a[m].y + og * o.y;
            rr.z = gg * a[m].z + og * o.z;
            rr.w = gg * a[m].w + og * o.w;
            *reinterpret_cast<float4*>(Out + off + 4*m) = rr;
        }
    }
}

extern "C" void kernel_launch(void* const* d_in, const int* in_sizes, int n_in,
                              void* d_out, int out_size) {
    // metadata order: inputs(0), query(1), key(2), value(3), outputs(4),
    //                 gate(5), key_memories(6), value_memories(7)
    const float* query   = (const float*)d_in[1];
    const float* outputs = (const float*)d_in[4];
    const float* gate    = (const float*)d_in[5];
    const float* kmem    = (const float*)d_in[6];
    const float* vmem    = (const float*)d_in[7];
    float* out = (float*)d_out;

    const int nconv = (Hc * Mc * Dc) / (256 * 8);   // 16384 blocks
    convert_k_kernel<<<nconv, 256>>>(kmem);

    cudaFuncSetAttribute(praxis_mma_kernel,
                         cudaFuncAttributeMaxDynamicSharedMemorySize, SM_TOTAL);
    dim3 grid(NQ / TQ, Hc);   // 32 x 8 = 256 CTAs
    praxis_mma_kernel<<<grid, 256, SM_TOTAL>>>(query, outputs, gate, kmem, vmem, out);
}

// round 17
// speedup vs baseline: 8.4271x; 1.1547x over previous
#include <cuda_runtime.h>
#include <cuda_bf16.h>
#include <cstdint>
#include <cstddef>

#define FULLMASK 0xffffffffu

constexpr int Bc=2, Hc=8, Sc=2048, Dc=128, Mc=32768;
constexpr int NQ = Bc*Sc;          // 4096 queries per head
constexpr int TQ = 128;            // queries per CTA
constexpr int TILEK = 32;          // keys per staged tile
constexpr int KSTRB = 272;         // padded smem bytes per key row (136 bf16)
constexpr int TBYTES = TILEK*KSTRB;// 8704 per buffer
constexpr int NT = Mc/TILEK;       // 1024 tiles
constexpr int CAP = 64;            // per-row append buffer capacity
constexpr int KEEP = 24;           // compaction keep target (bf16 top-24 superset)

// smem layout (byte offsets)
constexpr int SM_KB   = 0;               // 3 x 8704 = 26112 K staging
constexpr int SM_AF   = 26112;           // A fragments: 8 warps x 4096 = 32768
constexpr int SM_TH   = 65536;           // f32 [128]
constexpr int SM_CNT  = 66048;           // u32 [128]
constexpr int SM_CSB  = 66560;           // f32 [128][64] = 32768
constexpr int SM_CIB  = 99328;           // u16 [128][64] = 16384
constexpr int SM_TOTAL= 115712;          // 2 CTAs/SM
// epilogue overlays (QS region dead after rescore)
constexpr int SM_FS = 0;                 // f32 [128][16]
constexpr int SM_FI = 8192;              // i32 [128][16]

__device__ __nv_bfloat16 g_kbf[(size_t)Hc*Mc*Dc];   // 64 MB bf16 keys

static __device__ __forceinline__ void cpasync16(uint32_t dst, const void* src) {
    asm volatile("cp.async.cg.shared.global [%0], [%1], 16;" :: "r"(dst), "l"(src));
}
#define CP_COMMIT() asm volatile("cp.async.commit_group;" ::: "memory")
#define CP_WAIT1()  asm volatile("cp.async.wait_group 1;" ::: "memory")
#define CP_WAIT0()  asm volatile("cp.async.wait_group 0;" ::: "memory")

static __device__ __forceinline__ uint32_t packbf(float lo, float hi) {
    __nv_bfloat162 p = __floats2bfloat162_rn(lo, hi);
    return *reinterpret_cast<uint32_t*>(&p);
}
static __device__ __forceinline__ uint32_t lds32(uint32_t a) {
    uint32_t r;
    asm volatile("ld.shared.b32 %0, [%1];" : "=r"(r) : "r"(a));
    return r;
}
static __device__ __forceinline__ void lds128(uint32_t a, uint32_t& r0, uint32_t& r1,
                                              uint32_t& r2, uint32_t& r3) {
    asm volatile("ld.shared.v4.b32 {%0,%1,%2,%3}, [%4];"
                 : "=r"(r0), "=r"(r1), "=r"(r2), "=r"(r3) : "r"(a));
}
static __device__ __forceinline__ void sts128(uint32_t a, uint32_t r0, uint32_t r1,
                                              uint32_t r2, uint32_t r3) {
    asm volatile("st.shared.v4.b32 [%0], {%1,%2,%3,%4};"
                 :: "r"(a), "r"(r0), "r"(r1), "r"(r2), "r"(r3) : "memory");
}
static __device__ __forceinline__ void mma16816(float& c0, float& c1, float& c2, float& c3,
                                                uint32_t a0, uint32_t a1, uint32_t a2, uint32_t a3,
                                                uint32_t b0, uint32_t b1) {
    asm volatile("mma.sync.aligned.m16n8k16.row.col.f32.bf16.bf16.f32 "
                 "{%0,%1,%2,%3}, {%4,%5,%6,%7}, {%8,%9}, {%0,%1,%2,%3};"
                 : "+f"(c0), "+f"(c1), "+f"(c2), "+f"(c3)
                 : "r"(a0), "r"(a1), "r"(a2), "r"(a3), "r"(b0), "r"(b1));
}

__global__ void __launch_bounds__(256) convert_k_kernel(const float* __restrict__ K) {
    size_t i = ((size_t)blockIdx.x*256u + threadIdx.x) * 8u;
    float4 a = *reinterpret_cast<const float4*>(K+i);
    float4 b = *reinterpret_cast<const float4*>(K+i+4);
    __nv_bfloat162* o = reinterpret_cast<__nv_bfloat162*>(g_kbf+i);
    o[0] = __floats2bfloat162_rn(a.x,a.y);
    o[1] = __floats2bfloat162_rn(a.z,a.w);
    o[2] = __floats2bfloat162_rn(b.x,b.y);
    o[3] = __floats2bfloat162_rn(b.z,b.w);
}

__global__ __launch_bounds__(256, 2)
void praxis_mma_kernel(const float* __restrict__ Q,
                       const float* __restrict__ Outp,
                       const float* __restrict__ Gate,
                       const float* __restrict__ Kmem,
                       const float* __restrict__ Vmem,
                       float* __restrict__ Out)
{
    extern __shared__ char smem[];
    float*    QSf = reinterpret_cast<float*>(smem);            // [d][q] fp32
    float*    Th  = reinterpret_cast<float*>(smem + SM_TH);    // [128]
    unsigned* Cnt = reinterpret_cast<unsigned*>(smem + SM_CNT);// [128]
    float*    CSb = reinterpret_cast<float*>(smem + SM_CSB);   // [128][64]
    uint16_t* CIb = reinterpret_cast<uint16_t*>(smem + SM_CIB);// [128][64]
    float*    FSp = reinterpret_cast<float*>(smem + SM_FS);
    int*      FIp = reinterpret_cast<int*>(smem + SM_FI);

    const int tid  = threadIdx.x;
    const int wid  = tid >> 5;
    const int lane = tid & 31;
    const int h    = blockIdx.y;
    const int q0   = blockIdx.x * TQ;

    const float* KH = Kmem + (size_t)h * Mc * Dc;
    const __nv_bfloat16* KB = g_kbf + (size_t)h * Mc * Dc;

    const uint32_t smem_u32 = (uint32_t)__cvta_generic_to_shared(smem);
    const uint32_t kb_u32 = smem_u32 + SM_KB;
    const uint32_t af_u32 = smem_u32 + SM_AF + wid*4096 + lane*16;

    // ---- init thresholds / counters / append buffers ----
    for (int i = tid; i < 128; i += 256) { Th[i] = -3e38f; Cnt[i] = 0u; }
    for (int i = tid; i < 128 * CAP; i += 256) { CSb[i] = -3e38f; CIb[i] = 0; }

    // ---- verbatim qn loader (EXACT R2 arithmetic; reused for rescore) ----
    #define LOAD_QN()                                                            \
    {   _Pragma("unroll")                                                        \
        for (int half = 0; half < 2; ++half) {                                   \
            const int q    = tid >> 2;                                           \
            const int part = tid & 3;                                            \
            const int qrow = half * 64 + q;                                      \
            const int qg   = q0 + qrow;                                          \
            const int bq   = qg >> 11;                                           \
            const int sq   = qg & 2047;                                          \
            const float* qp = Q + ((((size_t)bq*Hc + h)*Sc + sq)*Dc) + part*32;  \
            float4 v[8]; float ss = 0.f;                                         \
            _Pragma("unroll")                                                    \
            for (int r = 0; r < 8; ++r) {                                        \
                v[r] = reinterpret_cast<const float4*>(qp)[r];                   \
                ss += v[r].x*v[r].x + v[r].y*v[r].y + v[r].z*v[r].z + v[r].w*v[r].w; \
            }                                                                    \
            ss += __shfl_xor_sync(FULLMASK, ss, 1);                              \
            ss += __shfl_xor_sync(FULLMASK, ss, 2);                              \
            const float inv = 1.0f / fmaxf(sqrtf(ss), 1e-12f);                   \
            _Pragma("unroll")                                                    \
            for (int r = 0; r < 8; ++r) {                                        \
                const int d = part*32 + r*4;                                     \
                QSf[(d+0)*TQ + qrow] = v[r].x * inv;                             \
                QSf[(d+1)*TQ + qrow] = v[r].y * inv;                             \
                QSf[(d+2)*TQ + qrow] = v[r].z * inv;                             \
                QSf[(d+3)*TQ + qrow] = v[r].w * inv;                             \
            }                                                                    \
        }                                                                        \
    }

    LOAD_QN();
    __syncthreads();

    // ---- build A fragments in transient regs (warp w owns rows 16w..16w+15) --
    const int g  = lane >> 2;          // 0..7
    const int t4 = lane & 3;           // 0..3
    const int rA = wid*16 + g;
    const int rB = rA + 8;
    uint32_t afr[8][4];
    {
        #pragma unroll
        for (int ks = 0; ks < 8; ++ks) {
            const int k0 = t4*2 + ks*16;
            afr[ks][0] = packbf(QSf[(k0+0)*TQ + rA], QSf[(k0+1)*TQ + rA]);
            afr[ks][1] = packbf(QSf[(k0+0)*TQ + rB], QSf[(k0+1)*TQ + rB]);
            afr[ks][2] = packbf(QSf[(k0+8)*TQ + rA], QSf[(k0+9)*TQ + rA]);
            afr[ks][3] = packbf(QSf[(k0+8)*TQ + rB], QSf[(k0+9)*TQ + rB]);
        }
    }
    __syncthreads();   // all QSf reads done; region becomes KB + AF

    // ---- store A fragments to SMEM (AF) and start K staging ----
    #pragma unroll
    for (int ks = 0; ks < 8; ++ks)
        sts128(af_u32 + ks*512, afr[ks][0], afr[ks][1], afr[ks][2], afr[ks][3]);

    // ---- K staging: tile t -> buffer b (512 x 16B chunks, 2 per thread) ----
    #define LOADTILE(t, b)                                                       \
    {   _Pragma("unroll")                                                        \
        for (int _i = 0; _i < 2; ++_i) {                                         \
            const int _c = tid + 256*_i;                                         \
            const int _row = _c >> 4, _seg = _c & 15;                            \
            cpasync16(kb_u32 + (uint32_t)((b)*TBYTES + _row*KSTRB + _seg*16),    \
                      reinterpret_cast<const char*>(KB)                          \
                      + ((size_t)((t)*TILEK + _row))*256 + _seg*16);             \
        }                                                                        \
    }

    LOADTILE(0, 0) CP_COMMIT();
    LOADTILE(1, 1) CP_COMMIT();

    // append: slot via atomic counter; clamp guards smem
    #define APPEND(row_, s_, k_)                                                 \
    {   const unsigned _p = atomicAdd(&Cnt[row_], 1u);                           \
        if (_p < (unsigned)CAP) {                                                \
            CSb[(row_)*CAP + _p] = (s_);                                         \
            CIb[(row_)*CAP + _p] = (uint16_t)(k_);                               \
        }                                                                        \
    }

    // ---- main loop over 1024 key tiles ----
    #pragma unroll 1
    for (int t = 0; t < NT; ++t) {
        CP_WAIT1();
        __syncthreads();
        const uint32_t bpgu = kb_u32 + (uint32_t)((t % 3) * TBYTES) + g*KSTRB + t4*4;
        const float thA = Th[rA];
        const float thB = Th[rB];

        // 2 block-pairs of 8 keys; A fragments streamed from SMEM per ks
        #pragma unroll 1
        for (int pb = 0; pb < 2; ++pb) {
            const uint32_t bx = bpgu + (uint32_t)(pb*2    )*8*KSTRB;
            const uint32_t by = bpgu + (uint32_t)(pb*2 + 1)*8*KSTRB;
            float x0=0.f,x1=0.f,x2=0.f,x3=0.f;
            float y0=0.f,y1=0.f,y2=0.f,y3=0.f;
            #pragma unroll
            for (int ks = 0; ks < 8; ++ks) {
                uint32_t a0, a1, a2, a3;
                lds128(af_u32 + ks*512, a0, a1, a2, a3);
                const uint32_t xb0 = lds32(bx + ks*32);
                const uint32_t xb1 = lds32(bx + ks*32 + 16);
                mma16816(x0,x1,x2,x3, a0,a1,a2,a3, xb0,xb1);
                const uint32_t yb0 = lds32(by + ks*32);
                const uint32_t yb1 = lds32(by + ks*32 + 16);
                mma16816(y0,y1,y2,y3, a0,a1,a2,a3, yb0,yb1);
            }
            const int kbX = t*TILEK + (pb*2    )*8 + t4*2;
            const int kbY = t*TILEK + (pb*2 + 1)*8 + t4*2;
            if (x0 >= thA) APPEND(rA, x0, kbX)
            if (x1 >= thA) APPEND(rA, x1, kbX + 1)
            if (y0 >= thA) APPEND(rA, y0, kbY)
            if (y1 >= thA) APPEND(rA, y1, kbY + 1)
            if (x2 >= thB) APPEND(rB, x2, kbX)
            if (x3 >= thB) APPEND(rB, x3, kbX + 1)
            if (y2 >= thB) APPEND(rB, y2, kbY)
            if (y3 >= thB) APPEND(rB, y3, kbY + 1)
        }

        if (t + 2 < NT) { LOADTILE(t + 2, (t + 2) % 3) }
        CP_COMMIT();

        // ---- scheduled compaction (warp-local; tracker in transient regs) ----
        const unsigned u = (unsigned)(t + 1);
        const unsigned u3 = u / 3u;
        if ((((u & (u - 1u)) == 0u) ||
             ((u3 * 3u == u) && ((u3 & (u3 - 1u)) == 0u))) && (t + 1 < NT)) {
            __syncwarp();
            if (lane < 16) {
                const int row = wid * 16 + lane;
                float*    bs = CSb + row * CAP;
                uint16_t* bi = CIb + row * CAP;
                float tp[KEEP];
                #pragma unroll
                for (int j = 0; j < KEEP; ++j) tp[j] = -3e38f;
                float tmin = -3e38f;
                #pragma unroll 1
                for (int j = 0; j < CAP; ++j) {
                    const float v = bs[j];
                    if (v > tmin) {
                        int mj = 0; float mn = tp[0];
                        #pragma unroll
                        for (int q = 1; q < KEEP; ++q)
                            if (tp[q] < mn) { mn = tp[q]; mj = q; }
                        #pragma unroll
                        for (int q = 0; q < KEEP; ++q)
                            if (q == mj) tp[q] = v;
                        float nm = v;
                        #pragma unroll
                        for (int q = 0; q < KEEP; ++q) nm = fminf(nm, tp[q]);
                        tmin = nm;
                    }
                }
                // keep everything >= tmin (ties preserved), clear the rest
                int w = 0;
                #pragma unroll 1
                for (int j = 0; j < CAP; ++j) {
                    const float v = bs[j];
                    if (v >= tmin) { const uint16_t ii = bi[j]; bs[w] = v; bi[w] = ii; ++w; }
                }
                #pragma unroll 1
                for (int j = w; j < CAP; ++j) bs[j] = -3e38f;
                Th[row]  = tmin;
                Cnt[row] = (unsigned)w;
            }
            __syncwarp();
        }
    }
    CP_WAIT0();
    __syncthreads();

    // ---- rebuild fp32 qn (verbatim) and rescore candidates ----
    LOAD_QN();
    __syncthreads();
    {
        const int row  = tid >> 1;
        const int half = tid & 1;
        #pragma unroll 1
        for (int j = 0; j < 32; ++j) {
            const int sl = row*CAP + half*32 + j;
            if (CSb[sl] > -1e37f) {
                const int idx = (int)CIb[sl];
                const float4* kp = reinterpret_cast<const float4*>(KH + (size_t)idx * Dc);
                float s = 0.f;
                #pragma unroll
                for (int m = 0; m < 32; ++m) {
                    const float4 kv = kp[m];
                    s = fmaf(QSf[(4*m+0)*TQ + row], kv.x, s);
                    s = fmaf(QSf[(4*m+1)*TQ + row], kv.y, s);
                    s = fmaf(QSf[(4*m+2)*TQ + row], kv.z, s);
                    s = fmaf(QSf[(4*m+3)*TQ + row], kv.w, s);
                }
                CSb[sl] = s;
            }
        }
    }
    __syncthreads();

    // ---- select top-16, tie rule (score desc, index asc) ----
    if (tid < 128) {
        #pragma unroll 1
        for (int n = 0; n < 16; ++n) {
            float bs = -3e38f; int bi = 0x7fffffff; int bj = 0;
            #pragma unroll 1
            for (int j = 0; j < CAP; ++j) {
                const float v = CSb[tid*CAP + j];
                const int  vi = (int)CIb[tid*CAP + j];
                if (v > bs || (v == bs && vi < bi)) { bs = v; bi = vi; bj = j; }
            }
            FSp[tid*16 + n] = bs;
            FIp[tid*16 + n] = bi;
            CSb[tid*CAP + bj] = -3e38f;
        }
    }
    __syncthreads();

    // ---- epilogue: gather V, weighted sum, gate blend (verbatim) ----
    const float gv = Gate[h];
    const float gg = 1.0f / (1.0f + expf(-gv));
    const float og = 1.0f - gg;
    const float* VH = Vmem + (size_t)h * Mc * Dc;

    const int r    = tid >> 1;
    const int part = tid & 1;

    float4 a[16];
    #pragma unroll
    for (int m = 0; m < 16; ++m) a[m] = make_float4(0.f, 0.f, 0.f, 0.f);

    #pragma unroll 1
    for (int j = 0; j < 16; ++j) {
        const float sj = FSp[r*16 + j];
        const int   vj = FIp[r*16 + j];
        const float4* vp = reinterpret_cast<const float4*>(VH + (size_t)vj * Dc + part * 64);
        #pragma unroll
        for (int m = 0; m < 16; ++m) {
            const float4 v = vp[m];
            a[m].x += sj * v.x; a[m].y += sj * v.y;
            a[m].z += sj * v.z; a[m].w += sj * v.w;
        }
    }
    {
        const int qg = q0 + r;
        const int bq = qg >> 11;
        const int sq = qg & 2047;
        const size_t off = (((size_t)bq * Hc + h) * Sc + sq) * Dc + part * 64;
        #pragma unroll
        for (int m = 0; m < 16; ++m) {
            const float4 o = *reinterpret_cast<const float4*>(Outp + off + 4*m);
            float4 rr;
            rr.x = gg * a[m].x + og * o.x;
            rr.y = gg * a[m].y + og * o.y;
            rr.z = gg * a[m].z + og * o.z;
            rr.w = gg * a[m].w + og * o.w;
            *reinterpret_cast<float4*>(Out + off + 4*m) = rr;
        }
    }
}

extern "C" void kernel_launch(void* const* d_in, const int* in_sizes, int n_in,
                              void* d_out, int out_size) {
    // metadata order: inputs(0), query(1), key(2), value(3), outputs(4),
    //                 gate(5), key_memories(6), value_memories(7)
    const float* query   = (const float*)d_in[1];
    const float* outputs = (const float*)d_in[4];
    const float* gate    = (const float*)d_in[5];
    const float* kmem    = (const float*)d_in[6];
    const float* vmem    = (const float*)d_in[7];
    float* out = (float*)d_out;

    const int nconv = (Hc * Mc * Dc) / (256 * 8);   // 16384 blocks
    convert_k_kernel<<<nconv, 256>>>(kmem);

    cudaFuncSetAttribute(praxis_mma_kernel,
                         cudaFuncAttributeMaxDynamicSharedMemorySize, SM_TOTAL);
    dim3 grid(NQ / TQ, Hc);   // 32 x 8 = 256 CTAs
    praxis_mma_kernel<<<grid, 256, SM_TOTAL>>>(query, outputs, gate, kmem, vmem, out);
}